// round 11
// baseline (speedup 1.0000x reference)
#include <cuda_runtime.h>

#define N    8192
#define DIM  128
#define E    262144
#define ASTR 132   // padded A row stride (floats)

#define NB_MAC  128
#define NB_GW   256
#define NB_HIST 64
#define NB_BIG  (NB_MAC + NB_GW + NB_HIST)   // 448

// Scratch (device globals -- allocation-free; zero-init at load,
// g_M / g_cnt re-zeroed by k_final so each replay sees identical state)
__device__ float g_inv_nrm[N];
__device__ float g_dis[N];            // rsqrt(deg+1)
__device__ int   g_cnt[N];            // in-degree histogram
__device__ int   g_startA[N + 1];     // CSR starts + sentinel E
__device__ int   g_cursor[N];         // fill cursors
__device__ int   g_csr[E];            // CSR source node per slot
__device__ float g_M[DIM * DIM];      // Y^T x
__device__ float g_dxw[N * DIM];      // x @ W (unscaled)
__device__ float g_gate[N * DIM];     // sigmoid(y . M)

// =============== maccum panel (uses dynamic smem buffer) ==================
__device__ void maccum_panel(const float* __restrict__ x, float* sm,
                             int panel, int tid) {
    float* xs   = sm;              // [8][DIM]
    float* invs = sm + 8 * DIM;    // [8]
    int tx = tid & 15, ty = tid >> 4;
    int k0 = ty * 8, d0 = tx * 8;
    float acc[8][8] = {};
    int row_base = panel * 64;
    for (int p = 0; p < 8; p++) {
        int r0 = row_base + p * 8;
        {
            int rr = tid >> 5, cc = tid & 31;
            float4 v = ((const float4*)x)[(r0 + rr) * 32 + cc];
            ((float4*)&xs[rr * DIM])[cc] = v;
            float s = v.x * v.x + v.y * v.y + v.z * v.z + v.w * v.w;
            #pragma unroll
            for (int o = 16; o; o >>= 1) s += __shfl_xor_sync(0xffffffffu, s, o);
            if (cc == 0) {
                float inv = rsqrtf(s);
                invs[rr] = inv;
                g_inv_nrm[r0 + rr] = inv;
            }
        }
        __syncthreads();
        #pragma unroll
        for (int r = 0; r < 8; r++) {
            float inv = invs[r];
            float yk[8], xd[8];
            #pragma unroll
            for (int j = 0; j < 8; j++) yk[j] = xs[r * DIM + k0 + j] * inv;
            #pragma unroll
            for (int l = 0; l < 8; l++) xd[l] = xs[r * DIM + d0 + l];
            #pragma unroll
            for (int j = 0; j < 8; j++)
                #pragma unroll
                for (int l = 0; l < 8; l++)
                    acc[j][l] += yk[j] * xd[l];
        }
        __syncthreads();
    }
    #pragma unroll
    for (int j = 0; j < 8; j++)
        #pragma unroll
        for (int l = 0; l < 8; l++)
            atomicAdd(&g_M[(k0 + j) * DIM + (d0 + l)], acc[j][l]);
}

// =============== 32-row GEMM tile body (k-chunked float4 A loads) =========
// mode 0: B -> g_dxw (unscaled).  mode 1: B=g_M -> g_gate = sigmoid(.*inv)
__device__ void gemm_body(const float* __restrict__ x, const float* __restrict__ B,
                          float* sm, int rb, int mode, int tid) {
    float* As = sm;                 // [32][ASTR]
    float* Bs = sm + 32 * ASTR;     // [128][128]
    int tx = tid & 31, ty = tid >> 5;

    #pragma unroll
    for (int i = 0; i < 4; i++) {   // A: 32 rows x 32 float4
        int f = i * 256 + tid;
        int row = f >> 5, c4 = f & 31;
        float4 v = ((const float4*)x)[(rb + row) * 32 + c4];
        *((float4*)&As[row * ASTR + c4 * 4]) = v;
    }
    #pragma unroll
    for (int i = 0; i < 16; i++) {  // B: 4096 float4
        int f = i * 256 + tid;
        ((float4*)Bs)[f] = ((const float4*)B)[f];
    }
    __syncthreads();

    int r0 = ty * 4;
    float4 acc[4];
    #pragma unroll
    for (int i = 0; i < 4; i++) acc[i] = make_float4(0.f, 0.f, 0.f, 0.f);

    #pragma unroll 2
    for (int k0 = 0; k0 < DIM; k0 += 4) {
        float4 a[4];
        #pragma unroll
        for (int i = 0; i < 4; i++)
            a[i] = *(const float4*)&As[(r0 + i) * ASTR + k0];  // broadcast LDS.128
        #pragma unroll
        for (int kk = 0; kk < 4; kk++) {
            float4 bv = ((const float4*)Bs)[(k0 + kk) * 32 + tx];
            #pragma unroll
            for (int i = 0; i < 4; i++) {
                float av = ((const float*)&a[i])[kk];
                acc[i].x += av * bv.x; acc[i].y += av * bv.y;
                acc[i].z += av * bv.z; acc[i].w += av * bv.w;
            }
        }
    }

    if (mode == 0) {
        #pragma unroll
        for (int i = 0; i < 4; i++)
            ((float4*)g_dxw)[(rb + r0 + i) * 32 + tx] = acc[i];
    } else {
        #pragma unroll
        for (int i = 0; i < 4; i++) {
            int grow = rb + r0 + i;
            float s = g_inv_nrm[grow];
            float4 o;
            o.x = 1.f / (1.f + __expf(-acc[i].x * s));
            o.y = 1.f / (1.f + __expf(-acc[i].y * s));
            o.z = 1.f / (1.f + __expf(-acc[i].z * s));
            o.w = 1.f / (1.f + __expf(-acc[i].w * s));
            ((float4*)g_gate)[grow * 32 + tx] = o;
        }
    }
}

// =============== node 1: maccum | gemm-W | hist (role by blockIdx) ========
__global__ void __launch_bounds__(256) k_big1(const float* __restrict__ x,
                                              const int* __restrict__ ei,
                                              const float* __restrict__ W) {
    extern __shared__ float sm[];
    int tid = threadIdx.x, bid = blockIdx.x;
    if (bid < NB_MAC) {
        maccum_panel(x, sm, bid, tid);
    } else if (bid < NB_MAC + NB_GW) {
        gemm_body(x, W, sm, (bid - NB_MAC) * 32, 0, tid);
    } else {
        int hb = bid - NB_MAC - NB_GW;              // 0..NB_HIST-1
        const int4* c4p = (const int4*)(ei + E);
        for (int i = hb * 256 + tid; i < E / 4; i += NB_HIST * 256) {
            int4 c = __ldg(&c4p[i]);
            atomicAdd(&g_cnt[c.x], 1); atomicAdd(&g_cnt[c.y], 1);
            atomicAdd(&g_cnt[c.z], 1); atomicAdd(&g_cnt[c.w], 1);
        }
    }
}

// =============== node 3: gemm-M -> gate ===================================
__global__ void __launch_bounds__(256) k_gemmM(const float* __restrict__ x) {
    extern __shared__ float sm[];
    gemm_body(x, g_M, sm, blockIdx.x * 32, 1, threadIdx.x);
}

// =============== chain B: scan, then fill =================================
__global__ void k_scan() {
    __shared__ int warp_sums[32];
    int tid = threadIdx.x;            // 1024 threads, 8 counters each
    int base = tid * 8;
    int c[8], s = 0;
    #pragma unroll
    for (int j = 0; j < 8; j++) { c[j] = g_cnt[base + j]; s += c[j]; }
    int lane = tid & 31, w = tid >> 5;
    int v = s;
    #pragma unroll
    for (int o = 1; o < 32; o <<= 1) {
        int t = __shfl_up_sync(0xffffffffu, v, o);
        if (lane >= o) v += t;
    }
    if (lane == 31) warp_sums[w] = v;
    __syncthreads();
    if (w == 0) {
        int ws = warp_sums[lane];
        #pragma unroll
        for (int o = 1; o < 32; o <<= 1) {
            int t = __shfl_up_sync(0xffffffffu, ws, o);
            if (lane >= o) ws += t;
        }
        warp_sums[lane] = ws;
    }
    __syncthreads();
    int run = v - s + (w > 0 ? warp_sums[w - 1] : 0);
    #pragma unroll
    for (int j = 0; j < 8; j++) {
        g_startA[base + j] = run;
        g_cursor[base + j] = run;
        g_dis[base + j]    = rsqrtf((float)(c[j] + 1));
        run += c[j];
    }
    if (tid == 1023) g_startA[N] = E;
}

__global__ void k_fill(const int* __restrict__ ei) {
    int i = blockIdx.x * blockDim.x + threadIdx.x;
    int r = __ldg(&ei[i]);
    int c = __ldg(&ei[E + i]);
    g_csr[atomicAdd(&g_cursor[c], 1)] = r;
}

// =============== join: gather + gate + bias; self-clean g_M/g_cnt =========
__global__ void k_final(const float* __restrict__ b, float* __restrict__ out) {
    int tid = threadIdx.x;
    int gtid = blockIdx.x * 256 + tid;
    if (gtid < DIM * DIM) g_M[gtid] = 0.f;   // self-clean (not read below)
    if (gtid < N) g_cnt[gtid] = 0;

    int w = tid >> 5, lane = tid & 31;
    int node = blockIdx.x * 8 + w;
    const float4* dxw4 = (const float4*)g_dxw;

    int s0  = g_startA[node];
    int cnt = g_startA[node + 1] - s0;
    float dn = g_dis[node];
    float4 self = dxw4[node * 32 + lane];
    float4 acc;
    acc.x = self.x * dn; acc.y = self.y * dn;
    acc.z = self.z * dn; acc.w = self.w * dn;
    int j = 0;
    for (; j + 4 <= cnt; j += 4) {
        int i0 = __ldg(&g_csr[s0 + j]);
        int i1 = __ldg(&g_csr[s0 + j + 1]);
        int i2 = __ldg(&g_csr[s0 + j + 2]);
        int i3 = __ldg(&g_csr[s0 + j + 3]);
        float d0 = __ldg(&g_dis[i0]), d1 = __ldg(&g_dis[i1]);
        float d2 = __ldg(&g_dis[i2]), d3 = __ldg(&g_dis[i3]);
        float4 v0 = dxw4[i0 * 32 + lane];
        float4 v1 = dxw4[i1 * 32 + lane];
        float4 v2 = dxw4[i2 * 32 + lane];
        float4 v3 = dxw4[i3 * 32 + lane];
        acc.x += v0.x * d0 + v1.x * d1 + v2.x * d2 + v3.x * d3;
        acc.y += v0.y * d0 + v1.y * d1 + v2.y * d2 + v3.y * d3;
        acc.z += v0.z * d0 + v1.z * d1 + v2.z * d2 + v3.z * d3;
        acc.w += v0.w * d0 + v1.w * d1 + v2.w * d2 + v3.w * d3;
    }
    for (; j < cnt; j++) {
        int i0 = __ldg(&g_csr[s0 + j]);
        float d0 = __ldg(&g_dis[i0]);
        float4 v0 = dxw4[i0 * 32 + lane];
        acc.x += v0.x * d0; acc.y += v0.y * d0;
        acc.z += v0.z * d0; acc.w += v0.w * d0;
    }
    float4 bb = ((const float4*)b)[lane];
    float4 a  = ((const float4*)g_gate)[node * 32 + lane];
    float4 o;
    o.x = (acc.x * dn + bb.x) * a.x;
    o.y = (acc.y * dn + bb.y) * a.y;
    o.z = (acc.z * dn + bb.z) * a.z;
    o.w = (acc.w * dn + bb.w) * a.w;
    ((float4*)out)[node * 32 + lane] = o;
}

// ---------------------------------------------------------------- launcher
extern "C" void kernel_launch(void* const* d_in, const int* in_sizes, int n_in,
                              void* d_out, int out_size) {
    const float* x  = (const float*)d_in[0];
    const int*   ei = (const int*)d_in[1];
    const float* W  = (const float*)d_in[2];
    const float* b  = (const float*)d_in[3];
    float* out = (float*)d_out;

    const int SMEM_G = (32 * ASTR + 128 * 128) * 4;   // ~82.4 KB -> 2 blocks/SM
    static bool init_done = false;
    static cudaStream_t sB;
    static cudaEvent_t ev1, evB;
    if (!init_done) {
        cudaStreamCreateWithFlags(&sB, cudaStreamNonBlocking);
        cudaEventCreateWithFlags(&ev1, cudaEventDisableTiming);
        cudaEventCreateWithFlags(&evB, cudaEventDisableTiming);
        cudaFuncSetAttribute(k_big1,  cudaFuncAttributeMaxDynamicSharedMemorySize, SMEM_G);
        cudaFuncSetAttribute(k_gemmM, cudaFuncAttributeMaxDynamicSharedMemorySize, SMEM_G);
        init_done = true;
    }

    // node 1: maccum | gemm-W | hist
    k_big1<<<NB_BIG, 256, SMEM_G>>>(x, ei, W);
    cudaEventRecord(ev1, 0);

    // side chain: scan -> fill (overlaps gemm-M)
    cudaStreamWaitEvent(sB, ev1, 0);
    k_scan<<<1, 1024, 0, sB>>>();
    k_fill<<<E / 256, 256, 0, sB>>>(ei);
    cudaEventRecord(evB, sB);

    // main: gemm-M
    k_gemmM<<<N / 32, 256, SMEM_G>>>(x);

    // join: final
    cudaStreamWaitEvent(0, evB, 0);
    k_final<<<N / 8, 256>>>(b, out);
}